// round 3
// baseline (speedup 1.0000x reference)
#include <cuda_runtime.h>
#include <math.h>

#define NH 8
#define HD 64
#define SROW 512            // S*? no: row stride in elements of q/k/v = NH*HD
#define RS_QK 144           // Qpack/Kpack row stride (floats)
#define RS_V  72            // Vpack row stride (floats)
#define RS_P  72            // P row stride (floats)
#define OUT_ELEMS 2097152   // 4*1024*8*64
#define LSE_PER_RANK 8192   // 8*1024

__device__ __forceinline__ float tf32_rna(float x) {
    float y;
    asm("cvt.rna.tf32.f32 %0, %1;" : "=f"(y) : "f"(x));
    return y;
}

__device__ __forceinline__ void mma_tf32(float4& c,
    float a0, float a1, float a2, float a3, float b0, float b1)
{
    asm volatile(
        "mma.sync.aligned.m16n8k8.row.col.f32.tf32.tf32.f32 "
        "{%0,%1,%2,%3}, {%4,%5,%6,%7}, {%8,%9}, {%0,%1,%2,%3};\n"
        : "+f"(c.x), "+f"(c.y), "+f"(c.z), "+f"(c.w)
        : "r"(__float_as_uint(a0)), "r"(__float_as_uint(a1)),
          "r"(__float_as_uint(a2)), "r"(__float_as_uint(a3)),
          "r"(__float_as_uint(b0)), "r"(__float_as_uint(b1)));
}

__global__ __launch_bounds__(128) void zz_fa_tc_kernel(
    const float* __restrict__ q,
    const float* __restrict__ k,
    const float* __restrict__ v,
    float* __restrict__ out)
{
    extern __shared__ float sm[];
    float* Qpack = sm;                    // [64][144] {hi(c),hi(c+4),lo(c),lo(c+4)} per (kt,c)
    float* Kpack = Qpack + 64 * RS_QK;    // [64][144] same packing
    float* Vpack = Kpack + 64 * RS_QK;    // [64][72]  {V[kc8+c][n], V[kc8+c+4][n]} float2
    float* Pb    = Vpack + 64 * RS_V;     // [64][72]  P row-major

    const float4* Qp4 = reinterpret_cast<const float4*>(Qpack);
    const float4* Kp4 = reinterpret_cast<const float4*>(Kpack);
    const float2* Vp2 = reinterpret_cast<const float2*>(Vpack);
    float2*       Pp2 = reinterpret_cast<float2*>(Pb);

    const int qi = 63 - blockIdx.x;       // heavy tiles first
    const int h  = blockIdx.y;
    const int tid = threadIdx.x;
    const int w   = tid >> 5;             // warp 0..3, rows [w*16, w*16+16)
    const int lane = tid & 31;
    const int grp = lane >> 2;            // 0..7
    const int qd  = lane & 3;             // 0..3
    const int r0 = w * 16 + grp;
    const int r1 = r0 + 8;

    const int qbase = qi * 64;
    const float scale = 0.125f;

    // ---- pack Q once (scaled, hi/lo split) ----
    for (int idx = tid; idx < 64 * 16; idx += 128) {
        int row = idx >> 4;
        int d4  = (idx & 15) << 2;
        float4 qv = *reinterpret_cast<const float4*>(&q[(qbase + row) * SROW + h * HD + d4]);
        float vals[4] = {qv.x, qv.y, qv.z, qv.w};
#pragma unroll
        for (int j = 0; j < 4; j++) {
            int d = d4 + j;
            float val = vals[j] * scale;
            float hi = tf32_rna(val);
            float lo = tf32_rna(val - hi);
            int base = row * RS_QK + (d >> 3) * 16 + (d & 3) * 4 + ((d >> 2) & 1);
            Qpack[base]     = hi;
            Qpack[base + 2] = lo;
        }
    }

    float4 oacc[8];
    float m0 = -INFINITY, m1 = -INFINITY, l0 = 0.f, l1 = 0.f;
#pragma unroll
    for (int i = 0; i < 8; i++) oacc[i] = make_float4(0.f, 0.f, 0.f, 0.f);

    for (int jt = 0; jt <= qi; ++jt) {
        __syncthreads();                  // prev iter readers of Kpack/Vpack done
        const int kb = jt * 64;
        // ---- pack K (hi/lo) and V (rna) tiles ----
        for (int idx = tid; idx < 64 * 16; idx += 128) {
            int row = idx >> 4;
            int d4  = (idx & 15) << 2;
            int g = (kb + row) * SROW + h * HD + d4;
            float4 kv = *reinterpret_cast<const float4*>(&k[g]);
            float4 vv = *reinterpret_cast<const float4*>(&v[g]);
            float ka[4] = {kv.x, kv.y, kv.z, kv.w};
            float va[4] = {vv.x, vv.y, vv.z, vv.w};
#pragma unroll
            for (int j = 0; j < 4; j++) {
                int d = d4 + j;
                float hi = tf32_rna(ka[j]);
                float lo = tf32_rna(ka[j] - hi);
                int base = row * RS_QK + (d >> 3) * 16 + (d & 3) * 4 + ((d >> 2) & 1);
                Kpack[base]     = hi;
                Kpack[base + 2] = lo;
                // V: contraction dim = row (key pos), n = d
                Vpack[d * RS_V + (row >> 3) * 8 + (row & 3) * 2 + ((row >> 2) & 1)] = tf32_rna(va[j]);
            }
        }
        __syncthreads();

        // ---- S = Q K^T via 3xTF32 ----
        float4 sacc[8];
#pragma unroll
        for (int i = 0; i < 8; i++) sacc[i] = make_float4(0.f, 0.f, 0.f, 0.f);

#pragma unroll
        for (int kt = 0; kt < 8; kt++) {
            float4 qa = Qp4[r0 * 36 + kt * 4 + qd];   // {a0h,a2h,a0l,a2l}
            float4 qb = Qp4[r1 * 36 + kt * 4 + qd];   // {a1h,a3h,a1l,a3l}
#pragma unroll
            for (int nt = 0; nt < 8; nt++) {
                float4 kf = Kp4[(nt * 8 + grp) * 36 + kt * 4 + qd]; // {b0h,b1h,b0l,b1l}
                mma_tf32(sacc[nt], qa.x, qb.x, qa.y, qb.y, kf.x, kf.y); // hi*hi
                mma_tf32(sacc[nt], qa.z, qb.z, qa.w, qb.w, kf.x, kf.y); // lo*hi
                mma_tf32(sacc[nt], qa.x, qb.x, qa.y, qb.y, kf.z, kf.w); // hi*lo
            }
        }

        // ---- causal mask on diagonal tile ----
        if (jt == qi) {
#pragma unroll
            for (int nt = 0; nt < 8; nt++) {
                int c0 = nt * 8 + 2 * qd;
                if (c0     > r0) sacc[nt].x = -INFINITY;
                if (c0 + 1 > r0) sacc[nt].y = -INFINITY;
                if (c0     > r1) sacc[nt].z = -INFINITY;
                if (c0 + 1 > r1) sacc[nt].w = -INFINITY;
            }
        }

        // ---- online softmax (rows r0 -> x,y ; r1 -> z,w) ----
        float mx0 = -INFINITY, mx1 = -INFINITY;
#pragma unroll
        for (int nt = 0; nt < 8; nt++) {
            mx0 = fmaxf(mx0, fmaxf(sacc[nt].x, sacc[nt].y));
            mx1 = fmaxf(mx1, fmaxf(sacc[nt].z, sacc[nt].w));
        }
        mx0 = fmaxf(mx0, __shfl_xor_sync(0xffffffffu, mx0, 1));
        mx0 = fmaxf(mx0, __shfl_xor_sync(0xffffffffu, mx0, 2));
        mx1 = fmaxf(mx1, __shfl_xor_sync(0xffffffffu, mx1, 1));
        mx1 = fmaxf(mx1, __shfl_xor_sync(0xffffffffu, mx1, 2));

        float mn0 = fmaxf(m0, mx0), mn1 = fmaxf(m1, mx1);
        float al0 = __expf(m0 - mn0), al1 = __expf(m1 - mn1);
        float rs0 = 0.f, rs1 = 0.f;
#pragma unroll
        for (int nt = 0; nt < 8; nt++) {
            float px = __expf(sacc[nt].x - mn0);
            float py = __expf(sacc[nt].y - mn0);
            float pz = __expf(sacc[nt].z - mn1);
            float pw = __expf(sacc[nt].w - mn1);
            rs0 += px + py;
            rs1 += pz + pw;
            Pp2[r0 * 36 + nt * 4 + qd] = make_float2(tf32_rna(px), tf32_rna(py));
            Pp2[r1 * 36 + nt * 4 + qd] = make_float2(tf32_rna(pz), tf32_rna(pw));
        }
        rs0 += __shfl_xor_sync(0xffffffffu, rs0, 1);
        rs0 += __shfl_xor_sync(0xffffffffu, rs0, 2);
        rs1 += __shfl_xor_sync(0xffffffffu, rs1, 1);
        rs1 += __shfl_xor_sync(0xffffffffu, rs1, 2);
        l0 = l0 * al0 + rs0;  m0 = mn0;
        l1 = l1 * al1 + rs1;  m1 = mn1;
#pragma unroll
        for (int i = 0; i < 8; i++) {
            oacc[i].x *= al0; oacc[i].y *= al0;
            oacc[i].z *= al1; oacc[i].w *= al1;
        }
        __syncwarp();  // P written by quad-mates, read below within warp

        // ---- O += P V (single tf32) ----
#pragma unroll
        for (int kc = 0; kc < 8; kc++) {
            float a0 = Pb[r0 * RS_P + kc * 8 + qd];
            float a2 = Pb[r0 * RS_P + kc * 8 + qd + 4];
            float a1 = Pb[r1 * RS_P + kc * 8 + qd];
            float a3 = Pb[r1 * RS_P + kc * 8 + qd + 4];
#pragma unroll
            for (int dt = 0; dt < 8; dt++) {
                float2 bf = Vp2[(dt * 8 + grp) * 36 + kc * 4 + qd];
                mma_tf32(oacc[dt], a0, a1, a2, a3, bf.x, bf.y);
            }
        }
    }

    // ---- epilogue: normalize + zigzag scatter ----
    float inv0 = 1.f / l0, inv1 = 1.f / l1;
    int sg0 = qbase + r0, sg1 = qbase + r1;
    int c0g = sg0 >> 9, c1g = sg1 >> 9;
    int rk0 = (c0g < 4) ? c0g : 7 - c0g;
    int sl0 = (c0g < 4) ? (sg0 & 511) : 512 + (sg0 & 511);
    int rk1 = (c1g < 4) ? c1g : 7 - c1g;
    int sl1 = (c1g < 4) ? (sg1 & 511) : 512 + (sg1 & 511);
    int ob0 = rk0 * 524288 + sl0 * 512 + h * 64;
    int ob1 = rk1 * 524288 + sl1 * 512 + h * 64;
#pragma unroll
    for (int dt = 0; dt < 8; dt++) {
        int d = dt * 8 + 2 * qd;
        *reinterpret_cast<float2*>(&out[ob0 + d]) =
            make_float2(oacc[dt].x * inv0, oacc[dt].y * inv0);
        *reinterpret_cast<float2*>(&out[ob1 + d]) =
            make_float2(oacc[dt].z * inv1, oacc[dt].w * inv1);
    }
    if (qd == 0) {
        out[OUT_ELEMS + rk0 * LSE_PER_RANK + h * 1024 + sl0] = m0 + logf(l0);
        out[OUT_ELEMS + rk1 * LSE_PER_RANK + h * 1024 + sl1] = m1 + logf(l1);
    }
}

extern "C" void kernel_launch(void* const* d_in, const int* in_sizes, int n_in,
                              void* d_out, int out_size)
{
    const float* q = (const float*)d_in[0];
    const float* k = (const float*)d_in[1];
    const float* v = (const float*)d_in[2];
    float* out = (float*)d_out;

    const int smem_bytes = (64 * RS_QK * 2 + 64 * RS_V + 64 * RS_P) * (int)sizeof(float); // 110592
    static int configured = 0;
    cudaFuncSetAttribute(zz_fa_tc_kernel, cudaFuncAttributeMaxDynamicSharedMemorySize, smem_bytes);
    (void)configured;

    dim3 grid(64, NH);
    zz_fa_tc_kernel<<<grid, 128, smem_bytes>>>(q, k, v, out);
}

// round 6
// speedup vs baseline: 3.0273x; 3.0273x over previous
#include <cuda_runtime.h>
#include <cuda_bf16.h>
#include <math.h>
#include <stdint.h>

#define NH 8
#define GROW 512            // gmem row stride (NH*HD)
#define OUT_ELEMS 2097152   // 4*1024*8*64
#define QB_OFF 0            // Q packed bf16 hi/lo: 64 units * 528B
#define KB_OFF 33792        // K packed bf16 hi/lo: 64 keys * 320B
#define VP_OFF 54272        // V packed tf32: 64 d * 288B
#define PP_OFF 72704        // P packed tf32: 64 units * 544B
#define LP_OFF 107520       // row-sum partials: 2 * 128 floats
#define SMEM_TOTAL 108544

__device__ float g_scrO[512 * 8192];   // partial O: (h*32+qt)*2+half -> [128][64]
__device__ float g_scrL[512 * 128];    // partial l

__device__ __forceinline__ float tf32_rna(float x) {
    float y; asm("cvt.rna.tf32.f32 %0, %1;" : "=f"(y) : "f"(x)); return y;
}
__device__ __forceinline__ void mma_bf16(float4& c,
    uint32_t a0, uint32_t a1, uint32_t a2, uint32_t a3, uint32_t b0, uint32_t b1)
{
    asm volatile(
        "mma.sync.aligned.m16n8k16.row.col.f32.bf16.bf16.f32 "
        "{%0,%1,%2,%3}, {%4,%5,%6,%7}, {%8,%9}, {%0,%1,%2,%3};\n"
        : "+f"(c.x), "+f"(c.y), "+f"(c.z), "+f"(c.w)
        : "r"(a0), "r"(a1), "r"(a2), "r"(a3), "r"(b0), "r"(b1));
}
__device__ __forceinline__ void mma_tf32(float4& c,
    float a0, float a1, float a2, float a3, float b0, float b1)
{
    asm volatile(
        "mma.sync.aligned.m16n8k8.row.col.f32.tf32.tf32.f32 "
        "{%0,%1,%2,%3}, {%4,%5,%6,%7}, {%8,%9}, {%0,%1,%2,%3};\n"
        : "+f"(c.x), "+f"(c.y), "+f"(c.z), "+f"(c.w)
        : "r"(__float_as_uint(a0)), "r"(__float_as_uint(a1)),
          "r"(__float_as_uint(a2)), "r"(__float_as_uint(a3)),
          "r"(__float_as_uint(b0)), "r"(__float_as_uint(b1)));
}
__device__ __forceinline__ uint32_t pack2(float a, float b) {
    __nv_bfloat162 t = __floats2bfloat162_rn(a, b);
    return *reinterpret_cast<uint32_t*>(&t);
}

__global__ __launch_bounds__(256, 2) void zz_fa_part(
    const float* __restrict__ q,
    const float* __restrict__ k,
    const float* __restrict__ v)
{
    extern __shared__ char sm[];
    const int tid = threadIdx.x;
    const int w = tid >> 5, lane = tid & 31, grp = lane >> 2, qd = lane & 3;
    const int rslot = w >> 1, ch = w & 1;
    const int bx = blockIdx.x;
    const int qb = 31 - (bx >> 4);        // heavy q-tiles first
    const int h = (bx >> 1) & 7;
    const int half = bx & 1;
    const int qbase = qb * 128;

    // ---- pack Q once (scaled, bf16 hi/lo split) ----
    for (int idx = tid; idx < 2048; idx += 256) {
        int row = idx >> 4, d4 = (idx & 15) << 2;
        float4 qv = *reinterpret_cast<const float4*>(&q[(qbase + row) * GROW + h * 64 + d4]);
        float f0 = qv.x * 0.125f, f1 = qv.y * 0.125f, f2 = qv.z * 0.125f, f3 = qv.w * 0.125f;
        __nv_bfloat162 h01 = __floats2bfloat162_rn(f0, f1);
        __nv_bfloat162 h23 = __floats2bfloat162_rn(f2, f3);
        uint32_t hi01 = *reinterpret_cast<uint32_t*>(&h01);
        uint32_t hi23 = *reinterpret_cast<uint32_t*>(&h23);
        uint32_t lo01 = pack2(f0 - __bfloat162float(h01.x), f1 - __bfloat162float(h01.y));
        uint32_t lo23 = pack2(f2 - __bfloat162float(h23.x), f3 - __bfloat162float(h23.y));
        int mt = row >> 4, g = row & 7, rh = (row >> 3) & 1;
        int kt = d4 >> 4, dp = d4 & 15, hf = dp >> 3, qd0 = (dp & 7) >> 1;
        int comp = hf * 2 + rh;
        char* ub = sm + QB_OFF + (mt * 8 + g) * 528 + kt * 128;
        *reinterpret_cast<uint32_t*>(ub + qd0 * 32 + comp * 4) = hi01;
        *reinterpret_cast<uint32_t*>(ub + (qd0 + 1) * 32 + comp * 4) = hi23;
        *reinterpret_cast<uint32_t*>(ub + qd0 * 32 + 16 + comp * 4) = lo01;
        *reinterpret_cast<uint32_t*>(ub + (qd0 + 1) * 32 + 16 + comp * 4) = lo23;
    }

    float4 oacc[2][4];
    float lacc[2][2];
#pragma unroll
    for (int m = 0; m < 2; m++) {
        lacc[m][0] = 0.f; lacc[m][1] = 0.f;
#pragma unroll
        for (int j = 0; j < 4; j++) oacc[m][j] = make_float4(0.f, 0.f, 0.f, 0.f);
    }

    const int u0 = (rslot * 2) * 8 + grp;
    const int u1 = (rslot * 2 + 1) * 8 + grp;
    const int j0 = half ? (qb + 1) : 0;
    const int j1 = half ? (2 * qb + 1) : qb;

    for (int jt = j0; jt <= j1; ++jt) {
        __syncthreads();  // prior readers of Kb/Vp/Lp done

        // ---- pack K (bf16 hi/lo) and V (tf32, d-major) ----
        for (int idx = tid; idx < 1024; idx += 256) {
            int key = idx >> 4, d4 = (idx & 15) << 2;
            int goff = (jt * 64 + key) * GROW + h * 64 + d4;
            float4 kv = *reinterpret_cast<const float4*>(&k[goff]);
            float4 vv = *reinterpret_cast<const float4*>(&v[goff]);
            __nv_bfloat162 h01 = __floats2bfloat162_rn(kv.x, kv.y);
            __nv_bfloat162 h23 = __floats2bfloat162_rn(kv.z, kv.w);
            uint32_t hi01 = *reinterpret_cast<uint32_t*>(&h01);
            uint32_t hi23 = *reinterpret_cast<uint32_t*>(&h23);
            uint32_t lo01 = pack2(kv.x - __bfloat162float(h01.x), kv.y - __bfloat162float(h01.y));
            uint32_t lo23 = pack2(kv.z - __bfloat162float(h23.x), kv.w - __bfloat162float(h23.y));
            int kt = d4 >> 4, dp = d4 & 15, hf = dp >> 3, qd0 = (dp & 7) >> 1;
            char* kb_ = sm + KB_OFF + key * 320 + kt * 64;
            *reinterpret_cast<uint32_t*>(kb_ + qd0 * 16 + hf * 4) = hi01;
            *reinterpret_cast<uint32_t*>(kb_ + (qd0 + 1) * 16 + hf * 4) = hi23;
            *reinterpret_cast<uint32_t*>(kb_ + qd0 * 16 + 8 + hf * 4) = lo01;
            *reinterpret_cast<uint32_t*>(kb_ + (qd0 + 1) * 16 + 8 + hf * 4) = lo23;
            int kc = key >> 3, qv_ = key & 3, sel = (key >> 2) & 1;
            char* vb = sm + VP_OFF + kc * 32 + qv_ * 8 + sel * 4;
            *reinterpret_cast<float*>(vb + (d4 + 0) * 288) = tf32_rna(vv.x);
            *reinterpret_cast<float*>(vb + (d4 + 1) * 288) = tf32_rna(vv.y);
            *reinterpret_cast<float*>(vb + (d4 + 2) * 288) = tf32_rna(vv.z);
            *reinterpret_cast<float*>(vb + (d4 + 3) * 288) = tf32_rna(vv.w);
        }
        __syncthreads();

        // ---- GEMM1: S = Q K^T (2x bf16: hi*hi + lo*hi + hi*lo) ----
        float4 sacc[2][4];
#pragma unroll
        for (int m = 0; m < 2; m++)
#pragma unroll
            for (int n = 0; n < 4; n++) sacc[m][n] = make_float4(0.f, 0.f, 0.f, 0.f);

#pragma unroll
        for (int kt = 0; kt < 4; kt++) {
            const char* qp0 = sm + QB_OFF + u0 * 528 + kt * 128 + qd * 32;
            const char* qp1 = sm + QB_OFF + u1 * 528 + kt * 128 + qd * 32;
            uint4 qh0 = *reinterpret_cast<const uint4*>(qp0);
            uint4 ql0 = *reinterpret_cast<const uint4*>(qp0 + 16);
            uint4 qh1 = *reinterpret_cast<const uint4*>(qp1);
            uint4 ql1 = *reinterpret_cast<const uint4*>(qp1 + 16);
#pragma unroll
            for (int n = 0; n < 4; n++) {
                uint4 kf = *reinterpret_cast<const uint4*>(
                    sm + KB_OFF + ((ch * 4 + n) * 8 + grp) * 320 + kt * 64 + qd * 16);
                mma_bf16(sacc[0][n], qh0.x, qh0.y, qh0.z, qh0.w, kf.x, kf.y);
                mma_bf16(sacc[0][n], ql0.x, ql0.y, ql0.z, ql0.w, kf.x, kf.y);
                mma_bf16(sacc[0][n], qh0.x, qh0.y, qh0.z, qh0.w, kf.z, kf.w);
                mma_bf16(sacc[1][n], qh1.x, qh1.y, qh1.z, qh1.w, kf.x, kf.y);
                mma_bf16(sacc[1][n], ql1.x, ql1.y, ql1.z, ql1.w, kf.x, kf.y);
                mma_bf16(sacc[1][n], qh1.x, qh1.y, qh1.z, qh1.w, kf.z, kf.w);
            }
        }

        // ---- exp (+causal mask), P store (tf32), row sums ----
        const bool domask = (jt >= 2 * qb);
#pragma unroll
        for (int m = 0; m < 2; m++) {
            float rsA = 0.f, rsB = 0.f;
            int rA = (rslot * 2 + m) * 16 + grp;
            int gA = qbase + rA, gB = gA + 8;
#pragma unroll
            for (int n = 0; n < 4; n++) {
                int col0 = jt * 64 + (ch * 4 + n) * 8 + 2 * qd;
                float e0, e1, e2, e3;
                if (domask) {
                    e0 = (col0     <= gA) ? __expf(sacc[m][n].x) : 0.f;
                    e1 = (col0 + 1 <= gA) ? __expf(sacc[m][n].y) : 0.f;
                    e2 = (col0     <= gB) ? __expf(sacc[m][n].z) : 0.f;
                    e3 = (col0 + 1 <= gB) ? __expf(sacc[m][n].w) : 0.f;
                } else {
                    e0 = __expf(sacc[m][n].x); e1 = __expf(sacc[m][n].y);
                    e2 = __expf(sacc[m][n].z); e3 = __expf(sacc[m][n].w);
                }
                rsA += e0 + e1; rsB += e2 + e3;
                *reinterpret_cast<float4*>(
                    sm + PP_OFF + ((rslot * 2 + m) * 8 + grp) * 544 + (ch * 4 + n) * 64 + qd * 16) =
                    make_float4(tf32_rna(e0), tf32_rna(e2), tf32_rna(e1), tf32_rna(e3));
            }
            rsA += __shfl_xor_sync(0xffffffffu, rsA, 1);
            rsA += __shfl_xor_sync(0xffffffffu, rsA, 2);
            rsB += __shfl_xor_sync(0xffffffffu, rsB, 1);
            rsB += __shfl_xor_sync(0xffffffffu, rsB, 2);
            if (qd == 0) {
                float* lp = reinterpret_cast<float*>(sm + LP_OFF);
                lp[ch * 128 + rA] = rsA;
                lp[ch * 128 + rA + 8] = rsB;
            }
        }
        __syncthreads();

        // ---- GEMM2: O += P V (tf32), d-half per warp ----
#pragma unroll
        for (int kc = 0; kc < 8; kc++) {
            const char* p0 = sm + PP_OFF + u0 * 544 + kc * 64 + qd * 8;
            const char* p1 = sm + PP_OFF + u1 * 544 + kc * 64 + qd * 8;
            float2 a01 = *reinterpret_cast<const float2*>(p0);
            float2 a23 = *reinterpret_cast<const float2*>(p0 + 32);
            float2 b01 = *reinterpret_cast<const float2*>(p1);
            float2 b23 = *reinterpret_cast<const float2*>(p1 + 32);
#pragma unroll
            for (int j = 0; j < 4; j++) {
                float2 vv2 = *reinterpret_cast<const float2*>(
                    sm + VP_OFF + ((ch * 4 + j) * 8 + grp) * 288 + kc * 32 + qd * 8);
                mma_tf32(oacc[0][j], a01.x, a01.y, a23.x, a23.y, vv2.x, vv2.y);
                mma_tf32(oacc[1][j], b01.x, b01.y, b23.x, b23.y, vv2.x, vv2.y);
            }
        }
        {
            const float* lp = reinterpret_cast<const float*>(sm + LP_OFF);
#pragma unroll
            for (int m = 0; m < 2; m++) {
                int rA = (rslot * 2 + m) * 16 + grp;
                lacc[m][0] += lp[rA] + lp[128 + rA];
                lacc[m][1] += lp[rA + 8] + lp[128 + rA + 8];
            }
        }
    }

    // ---- write partials to scratch ----
    const int p = (h * 32 + qb) * 2 + half;
    float* Os = g_scrO + p * 8192;
#pragma unroll
    for (int m = 0; m < 2; m++) {
        int rA = (rslot * 2 + m) * 16 + grp, rB = rA + 8;
#pragma unroll
        for (int j = 0; j < 4; j++) {
            int db = (ch * 4 + j) * 8 + 2 * qd;
            *reinterpret_cast<float2*>(&Os[rA * 64 + db]) = make_float2(oacc[m][j].x, oacc[m][j].y);
            *reinterpret_cast<float2*>(&Os[rB * 64 + db]) = make_float2(oacc[m][j].z, oacc[m][j].w);
        }
        if (qd == 0) {
            g_scrL[p * 128 + rA] = lacc[m][0];
            g_scrL[p * 128 + rB] = lacc[m][1];
        }
    }
}

__global__ __launch_bounds__(256) void zz_fa_combine(float* __restrict__ out)
{
    __shared__ float inv_s[128];
    __shared__ float lse_s[128];
    const int b = blockIdx.x;
    const int qt = b >> 3, h = b & 7;
    const int p0 = (h * 32 + qt) * 2, p1 = p0 + 1;
    const int t = threadIdx.x;
    if (t < 128) {
        float l = g_scrL[p0 * 128 + t] + g_scrL[p1 * 128 + t];
        inv_s[t] = 1.f / l;
        lse_s[t] = logf(l);
    }
    __syncthreads();
    const float2* A = reinterpret_cast<const float2*>(g_scrO + p0 * 8192);
    const float2* B = reinterpret_cast<const float2*>(g_scrO + p1 * 8192);
#pragma unroll
    for (int i = 0; i < 16; i++) {
        int idx = t + i * 256;
        int row = idx >> 5, d2 = idx & 31;
        float2 a = A[idx], bb = B[idx];
        float iv = inv_s[row];
        int sg = qt * 128 + row;
        int c = sg >> 9;
        int rk = (c < 4) ? c : 7 - c;
        int sl = (c < 4) ? (sg & 511) : 512 + (sg & 511);
        *reinterpret_cast<float2*>(&out[rk * 524288 + sl * 512 + h * 64 + d2 * 2]) =
            make_float2((a.x + bb.x) * iv, (a.y + bb.y) * iv);
    }
    if (t < 128) {
        int sg = qt * 128 + t;
        int c = sg >> 9;
        int rk = (c < 4) ? c : 7 - c;
        int sl = (c < 4) ? (sg & 511) : 512 + (sg & 511);
        out[OUT_ELEMS + rk * 8192 + h * 1024 + sl] = lse_s[t];
    }
}

extern "C" void kernel_launch(void* const* d_in, const int* in_sizes, int n_in,
                              void* d_out, int out_size)
{
    const float* q = (const float*)d_in[0];
    const float* k = (const float*)d_in[1];
    const float* v = (const float*)d_in[2];
    float* out = (float*)d_out;

    cudaFuncSetAttribute(zz_fa_part, cudaFuncAttributeMaxDynamicSharedMemorySize, SMEM_TOTAL);
    zz_fa_part<<<512, 256, SMEM_TOTAL>>>(q, k, v);
    zz_fa_combine<<<256, 256>>>(out);
}

// round 7
// speedup vs baseline: 4.2273x; 1.3964x over previous
#include <cuda_runtime.h>
#include <cuda_bf16.h>
#include <math.h>
#include <stdint.h>

#define NH 8
#define GROW 512            // gmem row stride (NH*HD)
#define OUT_ELEMS 2097152   // 4*1024*8*64
#define QB_OFF 0            // Q packed bf16 hi/lo: 64 units * 528B
#define KB_OFF 33792        // K packed bf16 hi/lo: 64 keys * 320B (image copy)
#define VP_OFF 54272        // V packed tf32: 64 d * 288B (image copy)
#define PP_OFF 72704        // P packed tf32: 64 units * 544B
#define LP_OFF 107520       // row-sum partials: 2 * 128 floats
#define SMEM_TOTAL 108544
#define KIMG_F4 1280        // 20480B / 16
#define VIMG_F4 1152        // 18432B / 16

__device__ float4 g_kimg[NH * 64 * KIMG_F4];   // packed K tile images
__device__ float4 g_vimg[NH * 64 * VIMG_F4];   // packed V tile images
__device__ float g_scrO[512 * 8192];           // partial O
__device__ float g_scrL[512 * 128];            // partial l

__device__ __forceinline__ float tf32_rna(float x) {
    float y; asm("cvt.rna.tf32.f32 %0, %1;" : "=f"(y) : "f"(x)); return y;
}
__device__ __forceinline__ void mma_bf16(float4& c,
    uint32_t a0, uint32_t a1, uint32_t a2, uint32_t a3, uint32_t b0, uint32_t b1)
{
    asm volatile(
        "mma.sync.aligned.m16n8k16.row.col.f32.bf16.bf16.f32 "
        "{%0,%1,%2,%3}, {%4,%5,%6,%7}, {%8,%9}, {%0,%1,%2,%3};\n"
        : "+f"(c.x), "+f"(c.y), "+f"(c.z), "+f"(c.w)
        : "r"(a0), "r"(a1), "r"(a2), "r"(a3), "r"(b0), "r"(b1));
}
__device__ __forceinline__ void mma_tf32(float4& c,
    float a0, float a1, float a2, float a3, float b0, float b1)
{
    asm volatile(
        "mma.sync.aligned.m16n8k8.row.col.f32.tf32.tf32.f32 "
        "{%0,%1,%2,%3}, {%4,%5,%6,%7}, {%8,%9}, {%0,%1,%2,%3};\n"
        : "+f"(c.x), "+f"(c.y), "+f"(c.z), "+f"(c.w)
        : "r"(__float_as_uint(a0)), "r"(__float_as_uint(a1)),
          "r"(__float_as_uint(a2)), "r"(__float_as_uint(a3)),
          "r"(__float_as_uint(b0)), "r"(__float_as_uint(b1)));
}
__device__ __forceinline__ uint32_t pack2(float a, float b) {
    __nv_bfloat162 t = __floats2bfloat162_rn(a, b);
    return *reinterpret_cast<uint32_t*>(&t);
}
__device__ __forceinline__ uint32_t smem_u32(const void* p) {
    uint32_t a;
    asm("{ .reg .u64 t; cvta.to.shared.u64 t, %1; cvt.u32.u64 %0, t; }" : "=r"(a) : "l"(p));
    return a;
}
__device__ __forceinline__ void cp16(uint32_t saddr, const void* g) {
    asm volatile("cp.async.cg.shared.global [%0], [%1], 16;" :: "r"(saddr), "l"(g) : "memory");
}
#define CP_COMMIT() asm volatile("cp.async.commit_group;" ::: "memory")
#define CP_WAIT1()  asm volatile("cp.async.wait_group 1;" ::: "memory")

// ---- prep: pack K/V tiles into gmem images (exact smem byte layout) ----
__global__ __launch_bounds__(256) void zz_prep(
    const float* __restrict__ k, const float* __restrict__ v)
{
    extern __shared__ char sm[];
    const int tid = threadIdx.x;
    const int jt = blockIdx.x, h = blockIdx.y;
    for (int idx = tid; idx < 1024; idx += 256) {
        int key = idx >> 4, d4 = (idx & 15) << 2;
        int goff = (jt * 64 + key) * GROW + h * 64 + d4;
        float4 kv = *reinterpret_cast<const float4*>(&k[goff]);
        float4 vv = *reinterpret_cast<const float4*>(&v[goff]);
        __nv_bfloat162 h01 = __floats2bfloat162_rn(kv.x, kv.y);
        __nv_bfloat162 h23 = __floats2bfloat162_rn(kv.z, kv.w);
        uint32_t hi01 = *reinterpret_cast<uint32_t*>(&h01);
        uint32_t hi23 = *reinterpret_cast<uint32_t*>(&h23);
        uint32_t lo01 = pack2(kv.x - __bfloat162float(h01.x), kv.y - __bfloat162float(h01.y));
        uint32_t lo23 = pack2(kv.z - __bfloat162float(h23.x), kv.w - __bfloat162float(h23.y));
        int kt = d4 >> 4, dp = d4 & 15, hf = dp >> 3, qd0 = (dp & 7) >> 1;
        char* kb_ = sm + key * 320 + kt * 64;
        *reinterpret_cast<uint32_t*>(kb_ + qd0 * 16 + hf * 4) = hi01;
        *reinterpret_cast<uint32_t*>(kb_ + (qd0 + 1) * 16 + hf * 4) = hi23;
        *reinterpret_cast<uint32_t*>(kb_ + qd0 * 16 + 8 + hf * 4) = lo01;
        *reinterpret_cast<uint32_t*>(kb_ + (qd0 + 1) * 16 + 8 + hf * 4) = lo23;
        int kc = key >> 3, qv_ = key & 3, sel = (key >> 2) & 1;
        char* vb = sm + 20480 + kc * 32 + qv_ * 8 + sel * 4;
        *reinterpret_cast<float*>(vb + (d4 + 0) * 288) = tf32_rna(vv.x);
        *reinterpret_cast<float*>(vb + (d4 + 1) * 288) = tf32_rna(vv.y);
        *reinterpret_cast<float*>(vb + (d4 + 2) * 288) = tf32_rna(vv.z);
        *reinterpret_cast<float*>(vb + (d4 + 3) * 288) = tf32_rna(vv.w);
    }
    __syncthreads();
    float4* dstK = g_kimg + (h * 64 + jt) * KIMG_F4;
    const float4* srcK = reinterpret_cast<const float4*>(sm);
    for (int i = tid; i < KIMG_F4; i += 256) dstK[i] = srcK[i];
    float4* dstV = g_vimg + (h * 64 + jt) * VIMG_F4;
    const float4* srcV = reinterpret_cast<const float4*>(sm + 20480);
    for (int i = tid; i < VIMG_F4; i += 256) dstV[i] = srcV[i];
}

__global__ __launch_bounds__(256, 2) void zz_fa_part(
    const float* __restrict__ q)
{
    extern __shared__ char sm[];
    const uint32_t sb = smem_u32(sm);
    const int tid = threadIdx.x;
    const int w = tid >> 5, lane = tid & 31, grp = lane >> 2, qd = lane & 3;
    const int rslot = w >> 1, ch = w & 1;
    const int bx = blockIdx.x;
    const int qb = 31 - (bx >> 4);        // heavy q-tiles first
    const int h = (bx >> 1) & 7;
    const int half = bx & 1;
    const int qbase = qb * 128;

    // ---- pack Q once (scale * log2e folded in, bf16 hi/lo split) ----
    const float qscale = 0.125f * 1.4426950408889634f;
    for (int idx = tid; idx < 2048; idx += 256) {
        int row = idx >> 4, d4 = (idx & 15) << 2;
        float4 qv = *reinterpret_cast<const float4*>(&q[(qbase + row) * GROW + h * 64 + d4]);
        float f0 = qv.x * qscale, f1 = qv.y * qscale, f2 = qv.z * qscale, f3 = qv.w * qscale;
        __nv_bfloat162 h01 = __floats2bfloat162_rn(f0, f1);
        __nv_bfloat162 h23 = __floats2bfloat162_rn(f2, f3);
        uint32_t hi01 = *reinterpret_cast<uint32_t*>(&h01);
        uint32_t hi23 = *reinterpret_cast<uint32_t*>(&h23);
        uint32_t lo01 = pack2(f0 - __bfloat162float(h01.x), f1 - __bfloat162float(h01.y));
        uint32_t lo23 = pack2(f2 - __bfloat162float(h23.x), f3 - __bfloat162float(h23.y));
        int mt = row >> 4, g = row & 7, rh = (row >> 3) & 1;
        int kt = d4 >> 4, dp = d4 & 15, hf = dp >> 3, qd0 = (dp & 7) >> 1;
        int comp = hf * 2 + rh;
        char* ub = sm + QB_OFF + (mt * 8 + g) * 528 + kt * 128;
        *reinterpret_cast<uint32_t*>(ub + qd0 * 32 + comp * 4) = hi01;
        *reinterpret_cast<uint32_t*>(ub + (qd0 + 1) * 32 + comp * 4) = hi23;
        *reinterpret_cast<uint32_t*>(ub + qd0 * 32 + 16 + comp * 4) = lo01;
        *reinterpret_cast<uint32_t*>(ub + (qd0 + 1) * 32 + 16 + comp * 4) = lo23;
    }

    float4 oacc[2][4];
    float lacc[2][2];
#pragma unroll
    for (int m = 0; m < 2; m++) {
        lacc[m][0] = 0.f; lacc[m][1] = 0.f;
#pragma unroll
        for (int j = 0; j < 4; j++) oacc[m][j] = make_float4(0.f, 0.f, 0.f, 0.f);
    }

    const int u0 = (rslot * 2) * 8 + grp;
    const int u1 = (rslot * 2 + 1) * 8 + grp;
    const int j0 = half ? (qb + 1) : 0;
    const int j1 = half ? (2 * qb + 1) : qb;

    // prologue: kick K(j0) then V(j0)
    {
        const char* gK = reinterpret_cast<const char*>(g_kimg + (h * 64 + j0) * KIMG_F4);
        for (int i = tid; i < KIMG_F4; i += 256) cp16(sb + KB_OFF + i * 16, gK + i * 16);
        CP_COMMIT();
        const char* gV = reinterpret_cast<const char*>(g_vimg + (h * 64 + j0) * VIMG_F4);
        for (int i = tid; i < VIMG_F4; i += 256) cp16(sb + VP_OFF + i * 16, gV + i * 16);
        CP_COMMIT();
    }
    __syncthreads();   // Q pack visible

    for (int jt = j0; jt <= j1; ++jt) {
        CP_WAIT1();        // K(jt) landed (V(jt) may pend)
        __syncthreads();   // all threads' K copies visible

        // ---- GEMM1: S = Q K^T (bf16: hi*hi + lo*hi + hi*lo) ----
        float4 sacc[2][4];
#pragma unroll
        for (int m = 0; m < 2; m++)
#pragma unroll
            for (int n = 0; n < 4; n++) sacc[m][n] = make_float4(0.f, 0.f, 0.f, 0.f);

#pragma unroll
        for (int kt = 0; kt < 4; kt++) {
            const char* qp0 = sm + QB_OFF + u0 * 528 + kt * 128 + qd * 32;
            const char* qp1 = sm + QB_OFF + u1 * 528 + kt * 128 + qd * 32;
            uint4 qh0 = *reinterpret_cast<const uint4*>(qp0);
            uint4 ql0 = *reinterpret_cast<const uint4*>(qp0 + 16);
            uint4 qh1 = *reinterpret_cast<const uint4*>(qp1);
            uint4 ql1 = *reinterpret_cast<const uint4*>(qp1 + 16);
#pragma unroll
            for (int n = 0; n < 4; n++) {
                uint4 kf = *reinterpret_cast<const uint4*>(
                    sm + KB_OFF + ((ch * 4 + n) * 8 + grp) * 320 + kt * 64 + qd * 16);
                mma_bf16(sacc[0][n], qh0.x, qh0.y, qh0.z, qh0.w, kf.x, kf.y);
                mma_bf16(sacc[0][n], ql0.x, ql0.y, ql0.z, ql0.w, kf.x, kf.y);
                mma_bf16(sacc[0][n], qh0.x, qh0.y, qh0.z, qh0.w, kf.z, kf.w);
                mma_bf16(sacc[1][n], qh1.x, qh1.y, qh1.z, qh1.w, kf.x, kf.y);
                mma_bf16(sacc[1][n], ql1.x, ql1.y, ql1.z, ql1.w, kf.x, kf.y);
                mma_bf16(sacc[1][n], qh1.x, qh1.y, qh1.z, qh1.w, kf.z, kf.w);
            }
        }
        __syncthreads();   // K fully consumed

        // prefetch K(jt+1) — lands during exp + GEMM2
        if (jt < j1) {
            const char* gK = reinterpret_cast<const char*>(g_kimg + (h * 64 + jt + 1) * KIMG_F4);
            for (int i = tid; i < KIMG_F4; i += 256) cp16(sb + KB_OFF + i * 16, gK + i * 16);
            CP_COMMIT();
        }

        // ---- exp2 (+causal mask), P store (tf32), row sums ----
        const bool domask = (jt >= 2 * qb);
#pragma unroll
        for (int m = 0; m < 2; m++) {
            float rsA = 0.f, rsB = 0.f;
            int rA = (rslot * 2 + m) * 16 + grp;
            int gA = qbase + rA, gB = gA + 8;
#pragma unroll
            for (int n = 0; n < 4; n++) {
                int col0 = jt * 64 + (ch * 4 + n) * 8 + 2 * qd;
                float e0, e1, e2, e3;
                if (domask) {
                    e0 = (col0     <= gA) ? exp2f(sacc[m][n].x) : 0.f;
                    e1 = (col0 + 1 <= gA) ? exp2f(sacc[m][n].y) : 0.f;
                    e2 = (col0     <= gB) ? exp2f(sacc[m][n].z) : 0.f;
                    e3 = (col0 + 1 <= gB) ? exp2f(sacc[m][n].w) : 0.f;
                } else {
                    e0 = exp2f(sacc[m][n].x); e1 = exp2f(sacc[m][n].y);
                    e2 = exp2f(sacc[m][n].z); e3 = exp2f(sacc[m][n].w);
                }
                rsA += e0 + e1; rsB += e2 + e3;
                *reinterpret_cast<float4*>(
                    sm + PP_OFF + ((rslot * 2 + m) * 8 + grp) * 544 + (ch * 4 + n) * 64 + qd * 16) =
                    make_float4(tf32_rna(e0), tf32_rna(e2), tf32_rna(e1), tf32_rna(e3));
            }
            rsA += __shfl_xor_sync(0xffffffffu, rsA, 1);
            rsA += __shfl_xor_sync(0xffffffffu, rsA, 2);
            rsB += __shfl_xor_sync(0xffffffffu, rsB, 1);
            rsB += __shfl_xor_sync(0xffffffffu, rsB, 2);
            if (qd == 0) {
                float* lp = reinterpret_cast<float*>(sm + LP_OFF);
                lp[ch * 128 + rA] = rsA;
                lp[ch * 128 + rA + 8] = rsB;
            }
        }
        CP_WAIT1();        // V(jt) landed (K(jt+1) may pend)
        __syncthreads();   // P, L, V visible to all

        // ---- GEMM2: O += P V (tf32) ----
#pragma unroll
        for (int kc = 0; kc < 8; kc++) {
            const char* p0 = sm + PP_OFF + u0 * 544 + kc * 64 + qd * 8;
            const char* p1 = sm + PP_OFF + u1 * 544 + kc * 64 + qd * 8;
            float2 a01 = *reinterpret_cast<const float2*>(p0);
            float2 a23 = *reinterpret_cast<const float2*>(p0 + 32);
            float2 b01 = *reinterpret_cast<const float2*>(p1);
            float2 b23 = *reinterpret_cast<const float2*>(p1 + 32);
#pragma unroll
            for (int j = 0; j < 4; j++) {
                float2 vv2 = *reinterpret_cast<const float2*>(
                    sm + VP_OFF + ((ch * 4 + j) * 8 + grp) * 288 + kc * 32 + qd * 8);
                mma_tf32(oacc[0][j], a01.x, a01.y, a23.x, a23.y, vv2.x, vv2.y);
                mma_tf32(oacc[1][j], b01.x, b01.y, b23.x, b23.y, vv2.x, vv2.y);
            }
        }
        {
            const float* lp = reinterpret_cast<const float*>(sm + LP_OFF);
#pragma unroll
            for (int m = 0; m < 2; m++) {
                int rA = (rslot * 2 + m) * 16 + grp;
                lacc[m][0] += lp[rA] + lp[128 + rA];
                lacc[m][1] += lp[rA + 8] + lp[128 + rA + 8];
            }
        }
        __syncthreads();   // V fully consumed

        // prefetch V(jt+1) — lands during next GEMM1
        if (jt < j1) {
            const char* gV = reinterpret_cast<const char*>(g_vimg + (h * 64 + jt + 1) * VIMG_F4);
            for (int i = tid; i < VIMG_F4; i += 256) cp16(sb + VP_OFF + i * 16, gV + i * 16);
            CP_COMMIT();
        }
    }

    // ---- write partials to scratch ----
    const int p = (h * 32 + qb) * 2 + half;
    float* Os = g_scrO + p * 8192;
#pragma unroll
    for (int m = 0; m < 2; m++) {
        int rA = (rslot * 2 + m) * 16 + grp, rB = rA + 8;
#pragma unroll
        for (int j = 0; j < 4; j++) {
            int db = (ch * 4 + j) * 8 + 2 * qd;
            *reinterpret_cast<float2*>(&Os[rA * 64 + db]) = make_float2(oacc[m][j].x, oacc[m][j].y);
            *reinterpret_cast<float2*>(&Os[rB * 64 + db]) = make_float2(oacc[m][j].z, oacc[m][j].w);
        }
        if (qd == 0) {
            g_scrL[p * 128 + rA] = lacc[m][0];
            g_scrL[p * 128 + rB] = lacc[m][1];
        }
    }
}

__global__ __launch_bounds__(256) void zz_fa_combine(float* __restrict__ out)
{
    __shared__ float inv_s[128];
    __shared__ float lse_s[128];
    const int b = blockIdx.x;
    const int qt = b >> 3, h = b & 7;
    const int p0 = (h * 32 + qt) * 2, p1 = p0 + 1;
    const int t = threadIdx.x;
    if (t < 128) {
        float l = g_scrL[p0 * 128 + t] + g_scrL[p1 * 128 + t];
        inv_s[t] = 1.f / l;
        lse_s[t] = logf(l);
    }
    __syncthreads();
    const float2* A = reinterpret_cast<const float2*>(g_scrO + p0 * 8192);
    const float2* B = reinterpret_cast<const float2*>(g_scrO + p1 * 8192);
#pragma unroll
    for (int i = 0; i < 16; i++) {
        int idx = t + i * 256;
        int row = idx >> 5, d2 = idx & 31;
        float2 a = A[idx], bb = B[idx];
        float iv = inv_s[row];
        int sg = qt * 128 + row;
        int c = sg >> 9;
        int rk = (c < 4) ? c : 7 - c;
        int sl = (c < 4) ? (sg & 511) : 512 + (sg & 511);
        *reinterpret_cast<float2*>(&out[rk * 524288 + sl * 512 + h * 64 + d2 * 2]) =
            make_float2((a.x + bb.x) * iv, (a.y + bb.y) * iv);
    }
    if (t < 128) {
        int sg = qt * 128 + t;
        int c = sg >> 9;
        int rk = (c < 4) ? c : 7 - c;
        int sl = (c < 4) ? (sg & 511) : 512 + (sg & 511);
        out[OUT_ELEMS + rk * 8192 + h * 1024 + sl] = lse_s[t];
    }
}

extern "C" void kernel_launch(void* const* d_in, const int* in_sizes, int n_in,
                              void* d_out, int out_size)
{
    const float* q = (const float*)d_in[0];
    const float* k = (const float*)d_in[1];
    const float* v = (const float*)d_in[2];
    float* out = (float*)d_out;

    cudaFuncSetAttribute(zz_fa_part, cudaFuncAttributeMaxDynamicSharedMemorySize, SMEM_TOTAL);
    dim3 pgrid(64, NH);
    zz_prep<<<pgrid, 256, 40960>>>(k, v);
    zz_fa_part<<<512, 256, SMEM_TOTAL>>>(q);
    zz_fa_combine<<<256, 256>>>(out);
}